// round 1
// baseline (speedup 1.0000x reference)
#include <cuda_runtime.h>
#include <cstdint>

// Problem constants (B=8, S=512, V=32000, D=4096, r=16, E=4)
#define TOKS   4096
#define SLEN   512
#define SPLITL 32
#define DDIM   4096
#define VDIM   32000
#define SCALE  2.0f   // lora_alpha / r = 32/16

__device__ int    g_is64;            // 1 if x buffer is int64, 0 if int32
__device__ float2 g_c[TOKS * 32];    // per-token duplicated c pairs {c,c}

__device__ __forceinline__ unsigned long long pk2(float lo, float hi) {
    unsigned long long r;
    asm("mov.b64 %0, {%1, %2};" : "=l"(r) : "f"(lo), "f"(hi));
    return r;
}
__device__ __forceinline__ unsigned long long add2(unsigned long long a, unsigned long long b) {
    unsigned long long r;
    asm("add.rn.f32x2 %0, %1, %2;" : "=l"(r) : "l"(a), "l"(b));
    return r;
}

// ---------------------------------------------------------------------------
// Kernel 0: detect whether x is stored as int64 or int32.
// If int64 (little-endian, values < 2^31), every odd 32-bit word of the first
// 4096 words is 0. If int32, those words are 2048 random tokens — all-zero is
// impossible. Reads only the first 4096 words (in-bounds for both dtypes).
// ---------------------------------------------------------------------------
__global__ void detect_k(const int* __restrict__ xw) {
    __shared__ int sh[256];
    int t = threadIdx.x;
    int acc = 0;
#pragma unroll
    for (int q = 0; q < 8; q++) acc |= xw[2 * t + 1 + q * 512];
    sh[t] = acc;
    __syncthreads();
    if (t == 0) {
        int o = 0;
        for (int j = 0; j < 256; j++) o |= sh[j];
        g_is64 = (o == 0) ? 1 : 0;
    }
}

// ---------------------------------------------------------------------------
// Kernel 1: per-token router softmax + A-column gather -> duplicated c pairs.
//   c[i][k]      = w0 * SCALE * A1[k, tok]     (k in [0,16))
//   c[i][16+k]   = w1 * SCALE * A2[k, tok]
// stored as float2 {c, c} so the main kernel can LDS.128 them straight into
// fma.rn.f32x2 operands.
// ---------------------------------------------------------------------------
__global__ void c_k(const void* __restrict__ xr,
                    const float* __restrict__ A1, const float* __restrict__ A2,
                    const float* __restrict__ Wi, const float* __restrict__ bi,
                    const float* __restrict__ Wt, const float* __restrict__ bt) {
    int i = blockIdx.x * blockDim.x + threadIdx.x;
    if (i >= TOKS) return;
    int tok = g_is64 ? (int)((const long long*)xr)[i] : ((const int*)xr)[i];
    int s = i & (SLEN - 1);
    const float* W = (s < SPLITL) ? Wi : Wt;
    const float* b = (s < SPLITL) ? bi : bt;
    float l0 = W[tok] + b[0];
    float l1 = W[VDIM + tok] + b[1];
    float w0 = 1.0f / (1.0f + expf(l1 - l0));
    float s0 = w0 * SCALE;
    float s1 = (1.0f - w0) * SCALE;
    float2* cp = g_c + (size_t)i * 32;
#pragma unroll
    for (int r = 0; r < 16; r++) {
        float c1 = s0 * A1[(size_t)r * VDIM + tok];
        cp[r] = make_float2(c1, c1);
    }
#pragma unroll
    for (int r = 0; r < 16; r++) {
        float c2 = s1 * A2[(size_t)r * VDIM + tok];
        cp[16 + r] = make_float2(c2, c2);
    }
}

// ---------------------------------------------------------------------------
// Kernel 2: fused output.
// Grid: (32 token-tiles of 128, 8 d-tiles of 512). Block: 256 threads.
// Each thread owns a d-pair (d0, d0+1): B1/B2 rows held in registers as 32
// packed f32x2 pairs, reused across 128 tokens. Per-token c pairs broadcast
// from smem (LDS.128, all lanes same address). Inner math is fma.rn.f32x2
// (2x scalar FFMA throughput). base gather + out store are LDG.64/STG.64,
// 256B contiguous per warp.
// ---------------------------------------------------------------------------
__global__ __launch_bounds__(256) void emb_k(
    const void* __restrict__ xr, const float* __restrict__ emb,
    const float* __restrict__ B1, const float* __restrict__ B2,
    float* __restrict__ out)
{
    __shared__ __align__(16) unsigned long long sc[128 * 32];
    __shared__ int stok[128];
    const int tid   = threadIdx.x;
    const int ttile = blockIdx.x;
    const int d0    = blockIdx.y * 512 + tid * 2;

    // --- B register pairs: Bp[k] = {Bmat[d0][k], Bmat[d0+1][k]} ---
    unsigned long long Bp[32];
    {
        const float4* p0 = (const float4*)(B1 + (size_t)d0 * 16);
        const float4* p1 = (const float4*)(B1 + (size_t)(d0 + 1) * 16);
#pragma unroll
        for (int q = 0; q < 4; q++) {
            float4 a = p0[q], b = p1[q];
            Bp[q * 4 + 0] = pk2(a.x, b.x);
            Bp[q * 4 + 1] = pk2(a.y, b.y);
            Bp[q * 4 + 2] = pk2(a.z, b.z);
            Bp[q * 4 + 3] = pk2(a.w, b.w);
        }
        const float4* q0 = (const float4*)(B2 + (size_t)d0 * 16);
        const float4* q1 = (const float4*)(B2 + (size_t)(d0 + 1) * 16);
#pragma unroll
        for (int q = 0; q < 4; q++) {
            float4 a = q0[q], b = q1[q];
            Bp[16 + q * 4 + 0] = pk2(a.x, b.x);
            Bp[16 + q * 4 + 1] = pk2(a.y, b.y);
            Bp[16 + q * 4 + 2] = pk2(a.z, b.z);
            Bp[16 + q * 4 + 3] = pk2(a.w, b.w);
        }
    }

    // --- stage c pairs for this token tile into smem (coalesced float4) ---
    {
        const float4* gc = (const float4*)(g_c + (size_t)ttile * 128 * 32);
        float4* s4 = (float4*)sc;
#pragma unroll
        for (int q = 0; q < 8; q++) s4[tid + q * 256] = gc[tid + q * 256];
    }
    if (tid < 128) {
        int i = ttile * 128 + tid;
        stok[tid] = g_is64 ? (int)((const long long*)xr)[i] : ((const int*)xr)[i];
    }
    __syncthreads();

    const size_t obase = (size_t)(ttile * 128) * DDIM + d0;
#pragma unroll 2
    for (int t = 0; t < 128; t++) {
        const int tok = stok[t];
        const float2 b2 = *(const float2*)(emb + (size_t)tok * DDIM + d0);
        unsigned long long acc0 = 0ull, acc1 = 0ull;
        const unsigned long long* cr = sc + t * 32;
#pragma unroll
        for (int k = 0; k < 32; k += 2) {
            ulonglong2 cc = *(const ulonglong2*)(cr + k);
            asm("fma.rn.f32x2 %0, %1, %2, %0;" : "+l"(acc0) : "l"(Bp[k]),     "l"(cc.x));
            asm("fma.rn.f32x2 %0, %1, %2, %0;" : "+l"(acc1) : "l"(Bp[k + 1]), "l"(cc.y));
        }
        unsigned long long r = add2(add2(acc0, acc1), pk2(b2.x, b2.y));
        *(unsigned long long*)(out + obase + (size_t)t * DDIM) = r;
    }
}

// ---------------------------------------------------------------------------
extern "C" void kernel_launch(void* const* d_in, const int* in_sizes, int n_in,
                              void* d_out, int out_size) {
    const void*  x   = d_in[0];
    const float* emb = (const float*)d_in[1];
    const float* A1  = (const float*)d_in[2];
    const float* B1  = (const float*)d_in[3];
    const float* A2  = (const float*)d_in[4];
    const float* B2  = (const float*)d_in[5];
    const float* Wi  = (const float*)d_in[6];
    const float* bi  = (const float*)d_in[7];
    const float* Wt  = (const float*)d_in[8];
    const float* bt  = (const float*)d_in[9];
    float* out = (float*)d_out;

    detect_k<<<1, 256>>>((const int*)x);
    c_k<<<TOKS / 128, 128>>>(x, A1, A2, Wi, bi, Wt, bt);
    emb_k<<<dim3(TOKS / 128, DDIM / 512), 256>>>(x, emb, B1, B2, out);
}

// round 2
// speedup vs baseline: 1.5137x; 1.5137x over previous
#include <cuda_runtime.h>
#include <cstdint>

// B=8, S=512, V=32000, D=4096, r=16, E=4
#define TOKS   4096
#define SLEN   512
#define SPLITL 32
#define DDIM   4096
#define VDIM   32000
#define SCALE  2.0f   // lora_alpha / r

typedef unsigned long long u64;

__device__ __forceinline__ u64 pk2(float lo, float hi) {
    u64 r; asm("mov.b64 %0, {%1, %2};" : "=l"(r) : "f"(lo), "f"(hi)); return r;
}
__device__ __forceinline__ void upk2(u64 v, float& lo, float& hi) {
    asm("mov.b64 {%0, %1}, %2;" : "=f"(lo), "=f"(hi) : "l"(v));
}
__device__ __forceinline__ u64 add2(u64 a, u64 b) {
    u64 r; asm("add.rn.f32x2 %0, %1, %2;" : "=l"(r) : "l"(a), "l"(b)); return r;
}
__device__ __forceinline__ void fma2(u64& acc, u64 a, u64 b) {
    asm("fma.rn.f32x2 %0, %1, %2, %0;" : "+l"(acc) : "l"(a), "l"(b));
}

// ---------------------------------------------------------------------------
// Single fused kernel. Grid (32 token-tiles, 8 d-tiles), 128 threads.
// Each thread owns 4 consecutive d's. B1/B2 rows live in 128 registers as
// packed f32x2 pairs, reused across 128 tokens. Per-token c vectors (router
// weight * SCALE * A columns) are computed in-block and broadcast from smem.
// Base-row gather is software-pipelined (prefetch depth 4, LDG.128).
//
// int64-vs-int32 detection per block: odd 32-bit words of the first 256
// x-words (in-bounds for both dtypes) are all zero iff x is int64
// (values < 32000). 128 random tokens all being zero is impossible.
// ---------------------------------------------------------------------------
__global__ __launch_bounds__(128) void fused_k(
    const int*   __restrict__ xw,
    const float* __restrict__ emb,
    const float* __restrict__ A1, const float* __restrict__ B1,
    const float* __restrict__ A2, const float* __restrict__ B2,
    const float* __restrict__ Wi, const float* __restrict__ bi,
    const float* __restrict__ Wt, const float* __restrict__ bt,
    float* __restrict__ out)
{
    __shared__ __align__(16) ulonglong2 sc2[16][128];  // [k-pair][token] {c,c} dup pairs
    __shared__ int      stok[128];
    __shared__ unsigned sdet[4];

    const int tid   = threadIdx.x;
    const int ttile = blockIdx.x;
    const int d0    = blockIdx.y * 512 + tid * 4;

    // --- dtype detection (no extra kernel) ---
    {
        int hiw = xw[2 * tid + 1];                       // words 1..255, safe for int32
        unsigned ball = __ballot_sync(0xffffffffu, hiw != 0);
        if ((tid & 31) == 0) sdet[tid >> 5] = ball;
    }

    // --- pack B rows d0..d0+3 into f32x2 register pairs (independent of sync) ---
    u64 Bp01[32], Bp23[32];
    {
        const float4* r0 = (const float4*)(B1 + (size_t)(d0 + 0) * 16);
        const float4* r1 = (const float4*)(B1 + (size_t)(d0 + 1) * 16);
        const float4* r2 = (const float4*)(B1 + (size_t)(d0 + 2) * 16);
        const float4* r3 = (const float4*)(B1 + (size_t)(d0 + 3) * 16);
#pragma unroll
        for (int q = 0; q < 4; q++) {
            float4 a = r0[q], b = r1[q], c = r2[q], d = r3[q];
            Bp01[q*4+0] = pk2(a.x, b.x); Bp23[q*4+0] = pk2(c.x, d.x);
            Bp01[q*4+1] = pk2(a.y, b.y); Bp23[q*4+1] = pk2(c.y, d.y);
            Bp01[q*4+2] = pk2(a.z, b.z); Bp23[q*4+2] = pk2(c.z, d.z);
            Bp01[q*4+3] = pk2(a.w, b.w); Bp23[q*4+3] = pk2(c.w, d.w);
        }
        const float4* s0 = (const float4*)(B2 + (size_t)(d0 + 0) * 16);
        const float4* s1 = (const float4*)(B2 + (size_t)(d0 + 1) * 16);
        const float4* s2 = (const float4*)(B2 + (size_t)(d0 + 2) * 16);
        const float4* s3 = (const float4*)(B2 + (size_t)(d0 + 3) * 16);
#pragma unroll
        for (int q = 0; q < 4; q++) {
            float4 a = s0[q], b = s1[q], c = s2[q], d = s3[q];
            Bp01[16+q*4+0] = pk2(a.x, b.x); Bp23[16+q*4+0] = pk2(c.x, d.x);
            Bp01[16+q*4+1] = pk2(a.y, b.y); Bp23[16+q*4+1] = pk2(c.y, d.y);
            Bp01[16+q*4+2] = pk2(a.z, b.z); Bp23[16+q*4+2] = pk2(c.z, d.z);
            Bp01[16+q*4+3] = pk2(a.w, b.w); Bp23[16+q*4+3] = pk2(c.w, d.w);
        }
    }
    __syncthreads();

    // --- per-token router + c vector (thread tid handles token tid of tile) ---
    {
        const bool is64 = ((sdet[0] | sdet[1] | sdet[2] | sdet[3]) == 0);
        const int  i    = ttile * 128 + tid;
        const int  tok  = is64 ? xw[2 * i] : xw[i];
        stok[tid] = tok;
        const int s = i & (SLEN - 1);
        const float* W = (s < SPLITL) ? Wi : Wt;
        const float* b = (s < SPLITL) ? bi : bt;
        float l0 = W[tok] + b[0];
        float l1 = W[VDIM + tok] + b[1];
        float w0 = 1.0f / (1.0f + expf(l1 - l0));
        float s0 = w0 * SCALE;
        float s1 = SCALE - s0;
        float c[32];
#pragma unroll
        for (int r = 0; r < 16; r++) c[r]      = s0 * A1[(size_t)r * VDIM + tok];
#pragma unroll
        for (int r = 0; r < 16; r++) c[16 + r] = s1 * A2[(size_t)r * VDIM + tok];
#pragma unroll
        for (int kk = 0; kk < 16; kk++) {
            ulonglong2 v;
            v.x = pk2(c[2 * kk],     c[2 * kk]);
            v.y = pk2(c[2 * kk + 1], c[2 * kk + 1]);
            sc2[kk][tid] = v;
        }
    }
    __syncthreads();

    // --- main loop: 128 tokens, prefetch depth 4 on the base gather ---
    const size_t ob = (size_t)(ttile * 128) * DDIM + d0;
    float4 pf[4];
#pragma unroll
    for (int j = 0; j < 4; j++)
        pf[j] = __ldg((const float4*)(emb + (size_t)stok[j] * DDIM + d0));

#pragma unroll 1
    for (int t0 = 0; t0 < 128; t0 += 4) {
        float4 cur[4];
#pragma unroll
        for (int j = 0; j < 4; j++) cur[j] = pf[j];
        if (t0 + 4 < 128) {
#pragma unroll
            for (int j = 0; j < 4; j++)
                pf[j] = __ldg((const float4*)(emb + (size_t)stok[t0 + 4 + j] * DDIM + d0));
        }
#pragma unroll
        for (int j = 0; j < 4; j++) {
            const int t = t0 + j;
            u64 a0 = 0ull, a1 = 0ull, a2 = 0ull, a3 = 0ull;
#pragma unroll
            for (int kk = 0; kk < 16; kk++) {
                ulonglong2 cc = sc2[kk][t];          // LDS.128 broadcast
                fma2(a0, Bp01[2 * kk],     cc.x);
                fma2(a1, Bp23[2 * kk],     cc.x);
                fma2(a2, Bp01[2 * kk + 1], cc.y);
                fma2(a3, Bp23[2 * kk + 1], cc.y);
            }
            u64 r01 = add2(add2(a0, a2), pk2(cur[j].x, cur[j].y));
            u64 r23 = add2(add2(a1, a3), pk2(cur[j].z, cur[j].w));
            float4 o;
            upk2(r01, o.x, o.y);
            upk2(r23, o.z, o.w);
            *(float4*)(out + ob + (size_t)t * DDIM) = o;
        }
    }
}

// ---------------------------------------------------------------------------
extern "C" void kernel_launch(void* const* d_in, const int* in_sizes, int n_in,
                              void* d_out, int out_size) {
    const int*   x   = (const int*)d_in[0];
    const float* emb = (const float*)d_in[1];
    const float* A1  = (const float*)d_in[2];
    const float* B1  = (const float*)d_in[3];
    const float* A2  = (const float*)d_in[4];
    const float* B2  = (const float*)d_in[5];
    const float* Wi  = (const float*)d_in[6];
    const float* bi  = (const float*)d_in[7];
    const float* Wt  = (const float*)d_in[8];
    const float* bt  = (const float*)d_in[9];
    float* out = (float*)d_out;

    fused_k<<<dim3(TOKS / 128, DDIM / 512), 128>>>(
        x, emb, A1, B1, A2, B2, Wi, bi, Wt, bt, out);
}